// round 6
// baseline (speedup 1.0000x reference)
#include <cuda_runtime.h>
#include <cuda_fp16.h>
#include <math.h>
#include <stdint.h>

#define N_ROWS 65536
#define IN_DIM 512
#define NEMB 4096
#define TILE_M 64

__device__ float    g_Qcodes[NEMB * IN_DIM];
__device__ float    g_ehalf[NEMB];
__device__ uint32_t g_emb_i8[NEMB * 16];     // int8 codebook, 64 B/code packed
__device__ __half   g_WinT[64 * 512];        // W_in^T fp16
__device__ int      g_idx[N_ROWS];
__device__ int      g_counts[NEMB];
__device__ double   g_loss;

#define ESCALE 520192.0f
#define XSCALE 48.0f

// ---- smem layout ----
#define SM_XI8  0        // x int8 [64 rows][64B] pitch 80   -> 5120
#define SM_B0   5120     // codes buf0 [128][64B] pitch 80   -> 10240
#define SM_B1   15360    // codes buf1                       -> 10240
#define SM_WPH  5120     // phase A: W' fp16 [64][272B] (over B0+B1)
#define SM_XP   25600    // x fp32 [64][68] pitch 272        -> 17408 ; phase A: A' fp16 [64][272B]
#define DYN_SMEM 43008

__device__ __forceinline__ uint32_t smem_u32(const void* p) {
    uint32_t a;
    asm("{ .reg .u64 t; cvta.to.shared.u64 t, %1; cvt.u32.u64 %0, t; }" : "=r"(a) : "l"(p));
    return a;
}
__device__ __forceinline__ void ldmx4(uint32_t r[4], uint32_t addr) {
    asm volatile("ldmatrix.sync.aligned.m8n8.x4.shared.b16 {%0,%1,%2,%3}, [%4];"
        : "=r"(r[0]), "=r"(r[1]), "=r"(r[2]), "=r"(r[3]) : "r"(addr));
}
__device__ __forceinline__ void mma16816(float d[4], const uint32_t a[4], const uint32_t b[2]) {
    asm volatile("mma.sync.aligned.m16n8k16.row.col.f32.f16.f16.f32 "
        "{%0,%1,%2,%3}, {%4,%5,%6,%7}, {%8,%9}, {%0,%1,%2,%3};"
        : "+f"(d[0]), "+f"(d[1]), "+f"(d[2]), "+f"(d[3])
        : "r"(a[0]), "r"(a[1]), "r"(a[2]), "r"(a[3]), "r"(b[0]), "r"(b[1]));
}
__device__ __forceinline__ void mma_i8(int d[4], const uint32_t a[4], uint32_t b0, uint32_t b1) {
    asm volatile("mma.sync.aligned.m16n8k32.row.col.s32.s8.s8.s32 "
        "{%0,%1,%2,%3}, {%4,%5,%6,%7}, {%8,%9}, {%0,%1,%2,%3};"
        : "+r"(d[0]), "+r"(d[1]), "+r"(d[2]), "+r"(d[3])
        : "r"(a[0]), "r"(a[1]), "r"(a[2]), "r"(a[3]), "r"(b0), "r"(b1));
}
__device__ __forceinline__ uint32_t h2(float a, float b) {
    __half2 h = __floats2half2_rn(a, b);
    return *(uint32_t*)&h;
}
__device__ __forceinline__ int q8(float v) {
    float c = fminf(fmaxf(v * (-XSCALE), -127.f), 127.f);
    return __float2int_rn(c);
}

__global__ void k_prep(const float* __restrict__ W_in) {
    int t = blockIdx.x * blockDim.x + threadIdx.x;   // 32768
    if (t < NEMB) g_counts[t] = 0;
    if (t == 0) g_loss = 0.0;
    int n = t >> 9, k = t & 511;
    g_WinT[t] = __float2half(W_in[k * 64 + n]);
}

__global__ void k_codes(const float* __restrict__ emb, const float* __restrict__ W_out,
                        const float* __restrict__ b_out) {
    __shared__ float es[16 * 64];
    int tid = threadIdx.x;
    int cb = blockIdx.x * 16;
    for (int i = tid; i < 16 * 64; i += 256) es[i] = emb[(size_t)cb * 64 + i];
    __syncthreads();
    if (tid < 16) {
        float s = 0.f;
        for (int k = 0; k < 64; k++) { float e = es[tid * 64 + k]; s = fmaf(e, e, s); }
        g_ehalf[cb + tid] = 0.5f * s;
    }
    // int8 pack: each thread one u32 (4 elems)
    {
        int base = tid * 4;
        uint32_t v = 0;
#pragma unroll
        for (int j = 0; j < 4; j++) {
            int q = __float2int_rn(es[base + j] * ESCALE);
            v |= (uint32_t)(q & 0xFF) << (8 * j);
        }
        g_emb_i8[cb * 16 + tid] = v;
    }
    float ax[16], ay[16];
#pragma unroll
    for (int c = 0; c < 16; c++) { ax[c] = 0.f; ay[c] = 0.f; }
    int c0 = tid * 2;
    for (int k = 0; k < 64; k++) {
        float2 w = *(const float2*)&W_out[(size_t)k * 512 + c0];
#pragma unroll
        for (int c = 0; c < 16; c++) {
            float e = es[c * 64 + k];
            ax[c] = fmaf(e, w.x, ax[c]);
            ay[c] = fmaf(e, w.y, ay[c]);
        }
    }
    float2 b = *(const float2*)&b_out[c0];
#pragma unroll
    for (int c = 0; c < 16; c++)
        *(float2*)&g_Qcodes[(size_t)(cb + c) * 512 + c0] = make_float2(ax[c] + b.x, ay[c] + b.y);
}

// int8 screen chunk: 128 codes, 16 groups of 8
__device__ __forceinline__ void screen_chunk(uint32_t bb, int chunkbase,
                                             const uint32_t A[2][4], int lane,
                                             int& pk0, int& pk1) {
#pragma unroll
    for (int g = 0; g < 16; g++) {
        uint32_t B[4];
        ldmx4(B, bb + (uint32_t)g * 640);
        int d[4] = {0, 0, 0, 0};
        mma_i8(d, A[0], B[0], B[1]);
        mma_i8(d, A[1], B[2], B[3]);
        int c0 = chunkbase + g * 8 + (lane & 3) * 2;
        pk0 = min(pk0, d[0] * 4096 + c0);
        pk0 = min(pk0, d[1] * 4096 + c0 + 1);
        pk1 = min(pk1, d[2] * 4096 + c0);
        pk1 = min(pk1, d[3] * 4096 + c0 + 1);
    }
}

__global__ __launch_bounds__(128, 4) void k_argmin3(
    const float* __restrict__ inputs, const float* __restrict__ b_in,
    const float* __restrict__ emb) {
    extern __shared__ char sm[];
    uint32_t sb = smem_u32(sm);
    int tid = threadIdx.x;
    int wid = tid >> 5;
    int lane = tid & 31;
    int rowbase = blockIdx.x * TILE_M;

    int a_row = (lane & 7) + (lane & 8);
    int a_k8 = ((lane >> 4) & 1) * 8;
    int b_row = (lane & 7) + ((lane >> 4) & 1) * 8;
    int b_k8 = ((lane >> 3) & 1) * 8;

    // ======== Phase A: x = inputs @ W_in + b_in via fp16 MMA ========
    float d[8][4];
#pragma unroll
    for (int nt = 0; nt < 8; nt++)
#pragma unroll
        for (int j = 0; j < 4; j++) d[nt][j] = 0.f;

    int lrow = tid >> 1, lkh = tid & 1;
    for (int kc = 0; kc < 4; kc++) {
        __syncthreads();
        {
            const float4* gi = (const float4*)(inputs + (size_t)(rowbase + lrow) * 512 + kc * 128 + lkh * 64);
            char* adst = sm + SM_XP + lrow * 272 + lkh * 128;
#pragma unroll
            for (int j = 0; j < 8; j++) {
                float4 v0 = gi[2 * j], v1 = gi[2 * j + 1];
                *(uint4*)(adst + j * 16) =
                    make_uint4(h2(v0.x, v0.y), h2(v0.z, v0.w), h2(v1.x, v1.y), h2(v1.z, v1.w));
            }
        }
        {
            const uint4* gw = (const uint4*)(g_WinT + (size_t)lrow * 512 + kc * 128 + lkh * 64);
            char* wdst = sm + SM_WPH + lrow * 272 + lkh * 128;
#pragma unroll
            for (int j = 0; j < 8; j++) *(uint4*)(wdst + j * 16) = gw[j];
        }
        __syncthreads();
        uint32_t abase = sb + SM_XP + (uint32_t)(wid * 16 + a_row) * 272 + a_k8 * 2;
        uint32_t bbase = sb + SM_WPH + (uint32_t)b_row * 272 + b_k8 * 2;
#pragma unroll
        for (int ks = 0; ks < 8; ks++) {
            uint32_t Af[4];
            ldmx4(Af, abase + ks * 32);
#pragma unroll
            for (int ng = 0; ng < 4; ng++) {
                uint32_t Bf[4];
                ldmx4(Bf, bbase + (uint32_t)ng * (16 * 272) + ks * 32);
                mma16816(d[ng * 2], Af, Bf + 0);
                mma16816(d[ng * 2 + 1], Af, Bf + 2);
            }
        }
    }
    __syncthreads();   // A'/W' regions dead

    // bias; x fp32 -> SM_XP; x int8 (negated) -> SM_XI8
    {
        float* x_p = (float*)(sm + SM_XP);
        int r0 = wid * 16 + (lane >> 2);
        int cbase = (lane & 3) * 2;
#pragma unroll
        for (int nt = 0; nt < 8; nt++) {
            float2 bv = *(const float2*)&b_in[nt * 8 + cbase];
            d[nt][0] += bv.x; d[nt][1] += bv.y;
            d[nt][2] += bv.x; d[nt][3] += bv.y;
            *(float2*)&x_p[r0 * 68 + nt * 8 + cbase] = make_float2(d[nt][0], d[nt][1]);
            *(float2*)&x_p[(r0 + 8) * 68 + nt * 8 + cbase] = make_float2(d[nt][2], d[nt][3]);
            int q0 = q8(d[nt][0]), q1 = q8(d[nt][1]);
            int q2 = q8(d[nt][2]), q3 = q8(d[nt][3]);
            *(uint16_t*)(sm + SM_XI8 + r0 * 80 + nt * 8 + cbase) =
                (uint16_t)((q0 & 0xFF) | ((q1 & 0xFF) << 8));
            *(uint16_t*)(sm + SM_XI8 + (r0 + 8) * 80 + nt * 8 + cbase) =
                (uint16_t)((q2 & 0xFF) | ((q3 & 0xFF) << 8));
        }
    }
    // stage codes chunk 0 -> B0
    {
        const uint4* gsrc = (const uint4*)g_emb_i8 + tid * 4;
        char* sdst = sm + SM_B0 + tid * 80;
#pragma unroll
        for (int j = 0; j < 4; j++) *(uint4*)(sdst + j * 16) = gsrc[j];
    }
    __syncthreads();

    // A int8 fragments (2 k-steps of 32 bytes)
    uint32_t A[2][4];
    {
        uint32_t arow_addr = sb + SM_XI8 +
            (uint32_t)(wid * 16 + (lane & 7) + ((lane >> 3) & 1) * 8) * 80 + ((lane >> 4) & 1) * 16;
        ldmx4(A[0], arow_addr);
        ldmx4(A[1], arow_addr + 32);
    }
    uint32_t b_lane = (uint32_t)(lane & 7) * 80 + ((lane >> 3) & 3) * 16;
    uint32_t bbuf[2] = {sb + SM_B0 + b_lane, sb + SM_B1 + b_lane};

    int pk0a = 0x7FFFFFFF, pk1a = 0x7FFFFFFF;   // chunks 0-15
    int pk0b = 0x7FFFFFFF, pk1b = 0x7FFFFFFF;   // chunks 16-31

#pragma unroll 1
    for (int i = 0; i < 16; i++) {
        uint4 pf[4];
        const uint4* gsrc = (const uint4*)g_emb_i8 + (size_t)(i + 1) * 512 + tid * 4;
#pragma unroll
        for (int j = 0; j < 4; j++) pf[j] = gsrc[j];
        screen_chunk(bbuf[i & 1], i * 128, A, lane, pk0a, pk1a);
        char* sdst = sm + ((i & 1) ? SM_B0 : SM_B1) + tid * 80;
#pragma unroll
        for (int j = 0; j < 4; j++) *(uint4*)(sdst + j * 16) = pf[j];
        __syncthreads();
    }
#pragma unroll 1
    for (int i = 16; i < 32; i++) {
        uint4 pf[4];
        bool havepf = (i + 1) < 32;
        if (havepf) {
            const uint4* gsrc = (const uint4*)g_emb_i8 + (size_t)(i + 1) * 512 + tid * 4;
#pragma unroll
            for (int j = 0; j < 4; j++) pf[j] = gsrc[j];
        }
        screen_chunk(bbuf[i & 1], i * 128, A, lane, pk0b, pk1b);
        if (havepf) {
            char* sdst = sm + ((i & 1) ? SM_B0 : SM_B1) + tid * 80;
#pragma unroll
            for (int j = 0; j < 4; j++) *(uint4*)(sdst + j * 16) = pf[j];
        }
        __syncthreads();
    }

    // ======== exact fp32 rescore: 8 candidates per row (2 per lane-quad lane) ========
    {
        const float* x_p = (const float*)(sm + SM_XP);
        int r0 = wid * 16 + (lane >> 2);
#pragma unroll
        for (int h = 0; h < 2; h++) {
            int row = r0 + h * 8;
            int ca = (h ? pk1a : pk0a) & 4095;
            int cb = (h ? pk1b : pk0b) & 4095;
            const float4* x4 = (const float4*)(x_p + row * 68);
            float sa = 0.f, sbv = 0.f;
            const float4* ea = (const float4*)(emb + (size_t)ca * 64);
            const float4* eb = (const float4*)(emb + (size_t)cb * 64);
#pragma unroll
            for (int d4 = 0; d4 < 16; d4++) {
                float4 xv = x4[d4];
                float4 e1 = ea[d4], e2 = eb[d4];
                sa = fmaf(xv.x, e1.x, sa); sa = fmaf(xv.y, e1.y, sa);
                sa = fmaf(xv.z, e1.z, sa); sa = fmaf(xv.w, e1.w, sa);
                sbv = fmaf(xv.x, e2.x, sbv); sbv = fmaf(xv.y, e2.y, sbv);
                sbv = fmaf(xv.z, e2.z, sbv); sbv = fmaf(xv.w, e2.w, sbv);
            }
            float s1 = __ldg(&g_ehalf[ca]) - sa;
            float s2 = __ldg(&g_ehalf[cb]) - sbv;
            float s = s1; int c = ca;
            if (s2 < s || (s2 == s && cb < c)) { s = s2; c = cb; }
#pragma unroll
            for (int off = 1; off <= 2; off <<= 1) {
                float os = __shfl_xor_sync(0xffffffffu, s, off);
                int oc = __shfl_xor_sync(0xffffffffu, c, off);
                if (os < s || (os == s && oc < c)) { s = os; c = oc; }
            }
            if ((lane & 3) == 0) {
                g_idx[rowbase + row] = c;
                atomicAdd(&g_counts[c], 1);
            }
        }
    }
}

__global__ void k_gather(const float* __restrict__ inputs, float* __restrict__ out) {
    const int nf4 = N_ROWS * IN_DIM / 4;
    float lsum = 0.f;
    const float4* in4 = (const float4*)inputs;
    float4* out4 = (float4*)out;
    const float4* q4p = (const float4*)g_Qcodes;
    for (int f = blockIdx.x * blockDim.x + threadIdx.x; f < nf4; f += gridDim.x * blockDim.x) {
        int row = f >> 7;
        int col = f & 127;
        int id = __ldg(&g_idx[row]);
        float4 q = q4p[(size_t)id * 128 + col];
        float4 a = in4[f];
        float dx = q.x - a.x, dy = q.y - a.y, dz = q.z - a.z, dw = q.w - a.w;
        out4[f] = make_float4(a.x + dx, a.y + dy, a.z + dz, a.w + dw);
        lsum = fmaf(dx, dx, fmaf(dy, dy, fmaf(dz, dz, fmaf(dw, dw, lsum))));
    }
    for (int o = 16; o > 0; o >>= 1) lsum += __shfl_down_sync(0xffffffffu, lsum, o);
    __shared__ float ws[8];
    int lane = threadIdx.x & 31, w = threadIdx.x >> 5;
    if (lane == 0) ws[w] = lsum;
    __syncthreads();
    if (w == 0) {
        float v = (lane < 8) ? ws[lane] : 0.f;
        for (int o = 4; o > 0; o >>= 1) v += __shfl_down_sync(0xffffffffu, v, o);
        if (lane == 0) atomicAdd(&g_loss, (double)v);
    }
}

__global__ void k_final(float* __restrict__ out, int out_size) {
    __shared__ float red[256];
    int tid = threadIdx.x;
    float s = 0.f;
    for (int i = tid; i < NEMB; i += 256) {
        float p = (float)g_counts[i] * (1.0f / 65536.0f);
        s += p * logf(p + 1e-10f);
    }
    red[tid] = s;
    __syncthreads();
    for (int st = 128; st > 0; st >>= 1) {
        if (tid < st) red[tid] += red[tid + st];
        __syncthreads();
    }
    if (tid == 0) {
        float m = (float)(g_loss * (1.0 / 33554432.0));
        out[out_size - 2] = m + 0.25f * m;
        out[out_size - 1] = expf(-red[0]);
    }
}

extern "C" void kernel_launch(void* const* d_in, const int* in_sizes, int n_in,
                              void* d_out, int out_size) {
    const float* inputs = (const float*)d_in[0];
    const float* emb    = (const float*)d_in[1];
    const float* W_in   = (const float*)d_in[2];
    const float* b_in   = (const float*)d_in[3];
    const float* W_out  = (const float*)d_in[4];
    const float* b_out  = (const float*)d_in[5];
    float* out = (float*)d_out;

    cudaFuncSetAttribute(k_argmin3, cudaFuncAttributeMaxDynamicSharedMemorySize, DYN_SMEM);

    k_prep<<<128, 256>>>(W_in);
    k_codes<<<NEMB / 16, 256>>>(emb, W_out, b_out);
    k_argmin3<<<N_ROWS / TILE_M, 128, DYN_SMEM>>>(inputs, b_in, emb);
    k_gather<<<8192, 256>>>(inputs, out);
    k_final<<<1, 256>>>(out, out_size);
}